// round 1
// baseline (speedup 1.0000x reference)
#include <cuda_runtime.h>

#define NTOK 3072
#define DMODEL 768
#define NHEAD 12
#define HDIM 64
#define NWF_CTAS 576   /* 24x24 tiles of Wf */

// ---------------- scratch (device globals: no allocation allowed) ----------
__device__ float g_qa[NTOK * DMODEL];
__device__ float g_ka[NTOK * DMODEL];
__device__ float g_Q[NTOK * DMODEL];
__device__ float g_K[NTOK * DMODEL];
__device__ float g_V[NTOK * DMODEL];
__device__ float g_Wf[(size_t)NTOK * NTOK];
__device__ float g_P[(size_t)NTOK * NTOK];
__device__ float g_R[NTOK * NHEAD];
__device__ float g_rowsum[NTOK];
__device__ float g_part[2 * NWF_CTAS];
__device__ float g_thr[2];
__device__ float g_att[NTOK * DMODEL];

// ---------------- fast exp on the FMA pipe (no MUFU) -----------------------
// exp(x) = 2^(x*log2e); magic-number round, degree-5 poly for 2^f, f in [-.5,.5]
// rel err ~3e-6 over the ranges used here (|arg| <= ~8).
__device__ __forceinline__ float fexp(float x) {
    float z = x * 1.44269504089f;
    float zf = z + 12582912.0f;                    // round-to-nearest int
    int e = __float_as_int(zf) - 0x4b400000;       // the integer part
    float f = z - (zf - 12582912.0f);              // f in [-0.5, 0.5]
    float p = 1.33336e-3f;
    p = fmaf(p, f, 9.61813e-3f);
    p = fmaf(p, f, 5.55041e-2f);
    p = fmaf(p, f, 2.40226507e-1f);
    p = fmaf(p, f, 6.93147182e-1f);
    p = fmaf(p, f, 1.0f);
    return __int_as_float(__float_as_int(p) + (e << 23));
}

// ---------------- block-wide all-reduce (deterministic) --------------------
__device__ __forceinline__ float blockAllReduce(float v, float* sh) {
    int lane = threadIdx.x & 31;
    int w = threadIdx.x >> 5;
    int nw = (blockDim.x + 31) >> 5;
#pragma unroll
    for (int o = 16; o > 0; o >>= 1) v += __shfl_xor_sync(0xffffffffu, v, o);
    __syncthreads();                // protect sh against previous use
    if (lane == 0) sh[w] = v;
    __syncthreads();
    if (w == 0) {
        float r = (lane < nw) ? sh[lane] : 0.0f;
#pragma unroll
        for (int o = 16; o > 0; o >>= 1) r += __shfl_xor_sync(0xffffffffu, r, o);
        if (lane == 0) sh[0] = r;
    }
    __syncthreads();
    return sh[0];
}

// ---------------- tiled GEMM building blocks -------------------------------
// Panels are 128 (rows/cols) x 16 (k), stored k-major in smem with pad 132.

// Load 128x16 panel from row-major src (element (row,k) = src[row*ld + k]),
// transposed into dst[k][row].
__device__ __forceinline__ void load_panel_T(float (&dst)[16][132],
                                             const float* __restrict__ src, int ld) {
    int t = threadIdx.x;
#pragma unroll
    for (int it = 0; it < 2; ++it) {
        int idx = t + it * 256;       // 0..511 float4 loads
        int row = idx >> 2;
        int kq = (idx & 3) << 2;
        float4 v = *reinterpret_cast<const float4*>(src + (size_t)row * ld + kq);
        dst[kq + 0][row] = v.x;
        dst[kq + 1][row] = v.y;
        dst[kq + 2][row] = v.z;
        dst[kq + 3][row] = v.w;
    }
}

// Load 16x128 panel from row-major src (element (k,c) = src[k*ld + c]) directly.
__device__ __forceinline__ void load_panel_N(float (&dst)[16][132],
                                             const float* __restrict__ src, int ld) {
    int t = threadIdx.x;
#pragma unroll
    for (int it = 0; it < 2; ++it) {
        int idx = t + it * 256;       // 0..511 float4
        int k = idx >> 5;
        int c = (idx & 31) << 2;
        *reinterpret_cast<float4*>(&dst[k][c]) =
            *reinterpret_cast<const float4*>(src + (size_t)k * ld + c);
    }
}

// 8x8 register-tile micro-kernel over a 16-deep k panel.
__device__ __forceinline__ void micro16(const float (&As)[16][132],
                                        const float (&Bs)[16][132],
                                        float (&acc)[8][8], int ty8, int tx8) {
#pragma unroll
    for (int k = 0; k < 16; ++k) {
        float4 a0 = *reinterpret_cast<const float4*>(&As[k][ty8]);
        float4 a1 = *reinterpret_cast<const float4*>(&As[k][ty8 + 4]);
        float4 b0 = *reinterpret_cast<const float4*>(&Bs[k][tx8]);
        float4 b1 = *reinterpret_cast<const float4*>(&Bs[k][tx8 + 4]);
        float a[8] = {a0.x, a0.y, a0.z, a0.w, a1.x, a1.y, a1.z, a1.w};
        float b[8] = {b0.x, b0.y, b0.z, b0.w, b1.x, b1.y, b1.z, b1.w};
#pragma unroll
        for (int u = 0; u < 8; ++u)
#pragma unroll
            for (int v = 0; v < 8; ++v)
                acc[u][v] = fmaf(a[u], b[v], acc[u][v]);
    }
}

// ---------------- K1: the five projections (NT GEMM + bias) ----------------
// z = 0: qa = h_a@Wq_a^T, 1: ka = h_a@Wk_a^T, 2: Q, 3: K, 4: V (from h_s)
__global__ __launch_bounds__(256) void k_proj(
    const float* __restrict__ h_a, const float* __restrict__ h_s,
    const float* __restrict__ W0, const float* __restrict__ B0,
    const float* __restrict__ W1, const float* __restrict__ B1,
    const float* __restrict__ W2, const float* __restrict__ B2,
    const float* __restrict__ W3, const float* __restrict__ B3,
    const float* __restrict__ W4, const float* __restrict__ B4) {
    __shared__ __align__(16) float As[16][132];
    __shared__ __align__(16) float Bs[16][132];
    const float* A;
    const float* W;
    const float* B;
    float* C;
    switch (blockIdx.z) {
        case 0: A = h_a; W = W0; B = B0; C = g_qa; break;
        case 1: A = h_a; W = W1; B = B1; C = g_ka; break;
        case 2: A = h_s; W = W2; B = B2; C = g_Q; break;
        case 3: A = h_s; W = W3; B = B3; C = g_K; break;
        default: A = h_s; W = W4; B = B4; C = g_V; break;
    }
    int i0 = blockIdx.y * 128, j0 = blockIdx.x * 128;
    int tid = threadIdx.x, ty8 = (tid >> 4) << 3, tx8 = (tid & 15) << 3;
    float acc[8][8] = {};
    for (int kt = 0; kt < DMODEL; kt += 16) {
        load_panel_T(As, A + (size_t)i0 * DMODEL + kt, DMODEL);
        load_panel_T(Bs, W + (size_t)j0 * DMODEL + kt, DMODEL);
        __syncthreads();
        micro16(As, Bs, acc, ty8, tx8);
        __syncthreads();
    }
#pragma unroll
    for (int u = 0; u < 8; ++u) {
        int row = i0 + ty8 + u;
#pragma unroll
        for (int v = 0; v < 8; ++v)
            C[(size_t)row * DMODEL + j0 + tx8 + v] = acc[u][v] + B[j0 + tx8 + v];
    }
}

// ---------------- K2a: per-head softmax denominators R[i,h] ----------------
__global__ __launch_bounds__(256) void k_hrowsum() {
    __shared__ __align__(16) float As[16][132];
    __shared__ __align__(16) float Bs[16][132];
    __shared__ float red[128][17];
    int h = blockIdx.x;            // 12
    int i0 = blockIdx.y * 128;     // 24
    int tid = threadIdx.x, ty8 = (tid >> 4) << 3, tx8 = (tid & 15) << 3;
    const float* Ah = g_qa + h * HDIM;
    const float* Bh = g_ka + h * HDIM;
    float rsum[8] = {};
    for (int j0 = 0; j0 < NTOK; j0 += 128) {
        float acc[8][8] = {};
#pragma unroll
        for (int kt = 0; kt < HDIM; kt += 16) {
            load_panel_T(As, Ah + (size_t)i0 * DMODEL + kt, DMODEL);
            load_panel_T(Bs, Bh + (size_t)j0 * DMODEL + kt, DMODEL);
            __syncthreads();
            micro16(As, Bs, acc, ty8, tx8);
            __syncthreads();
        }
#pragma unroll
        for (int u = 0; u < 8; ++u)
#pragma unroll
            for (int v = 0; v < 8; ++v) rsum[u] += fexp(acc[u][v] * 0.125f);
    }
#pragma unroll
    for (int u = 0; u < 8; ++u) red[ty8 + u][tid & 15] = rsum[u];
    __syncthreads();
    if (tid < 128) {
        float s = 0.0f;
#pragma unroll
        for (int t = 0; t < 16; ++t) s += red[tid][t];
        g_R[(i0 + tid) * NHEAD + h] = s;
    }
}

// ---------------- K2b: Wf = Wd * mean_h softmax_h, + stats partials --------
__global__ __launch_bounds__(256) void k_wf(const float* __restrict__ dep) {
    __shared__ __align__(16) float As[16][132];
    __shared__ __align__(16) float Bs[16][132];
    __shared__ float Rinv[128][NHEAD];
    __shared__ float sh[32];
    int i0 = blockIdx.y * 128, j0 = blockIdx.x * 128;
    int tid = threadIdx.x, ty8 = (tid >> 4) << 3, tx8 = (tid & 15) << 3;
    for (int idx = tid; idx < 128 * NHEAD; idx += 256)
        Rinv[idx / NHEAD][idx % NHEAD] =
            1.0f / g_R[(i0 + idx / NHEAD) * NHEAD + idx % NHEAD];
    float wacc[8][8] = {};
    for (int h = 0; h < NHEAD; ++h) {
        const float* Ah = g_qa + h * HDIM;
        const float* Bh = g_ka + h * HDIM;
        float acc[8][8] = {};
#pragma unroll
        for (int kt = 0; kt < HDIM; kt += 16) {
            load_panel_T(As, Ah + (size_t)i0 * DMODEL + kt, DMODEL);
            load_panel_T(Bs, Bh + (size_t)j0 * DMODEL + kt, DMODEL);
            __syncthreads();
            micro16(As, Bs, acc, ty8, tx8);
            __syncthreads();
        }
#pragma unroll
        for (int u = 0; u < 8; ++u) {
            float ir = Rinv[ty8 + u][h];
#pragma unroll
            for (int v = 0; v < 8; ++v)
                wacc[u][v] = fmaf(fexp(acc[u][v] * 0.125f), ir, wacc[u][v]);
        }
    }
    float lsum = 0.0f, lss = 0.0f;
    const float invH = 1.0f / (float)NHEAD;
#pragma unroll
    for (int u = 0; u < 8; ++u) {
        int row = i0 + ty8 + u;
#pragma unroll
        for (int v = 0; v < 8; ++v) {
            int col = j0 + tx8 + v;
            float d = dep[(size_t)row * NTOK + col];
            float wf = fexp(-0.5f * d * d) * (wacc[u][v] * invH);
            g_Wf[(size_t)row * NTOK + col] = wf;
            lsum += wf;
            lss += wf * wf;
        }
    }
    lsum = blockAllReduce(lsum, sh);
    lss = blockAllReduce(lss, sh);
    if (tid == 0) {
        int c = blockIdx.y * gridDim.x + blockIdx.x;
        g_part[c] = lsum;
        g_part[NWF_CTAS + c] = lss;
    }
}

// ---------------- K3: soft threshold (mean + 0.5*std, ddof=1) --------------
__global__ void k_thr() {
    __shared__ float sh[32];
    float s = g_part[threadIdx.x];
    float ss = g_part[NWF_CTAS + threadIdx.x];
    s = blockAllReduce(s, sh);
    ss = blockAllReduce(ss, sh);
    if (threadIdx.x == 0) {
        double M = (double)NTOK * (double)NTOK;
        double mean = (double)s / M;
        double var = ((double)ss - (double)s * (double)s / M) / (M - 1.0);
        if (var < 0.0) var = 0.0;
        float thr = (float)(mean + 0.5 * sqrt(var));
        g_thr[0] = thr;
        g_thr[1] = 1.0f / thr;
    }
}

// ---------------- K4a: P = exp(scores * Ww) --------------------------------
__global__ __launch_bounds__(256) void k_scores() {
    __shared__ __align__(16) float As[16][132];
    __shared__ __align__(16) float Bs[16][132];
    int i0 = blockIdx.y * 128, j0 = blockIdx.x * 128;
    int tid = threadIdx.x, ty8 = (tid >> 4) << 3, tx8 = (tid & 15) << 3;
    float acc[8][8] = {};
    for (int kt = 0; kt < DMODEL; kt += 16) {
        load_panel_T(As, g_Q + (size_t)i0 * DMODEL + kt, DMODEL);
        load_panel_T(Bs, g_K + (size_t)j0 * DMODEL + kt, DMODEL);
        __syncthreads();
        micro16(As, Bs, acc, ty8, tx8);
        __syncthreads();
    }
    float thr = g_thr[0], invthr = g_thr[1];
    const float sc = 0.03608439182435161f;  // 1/sqrt(768)
#pragma unroll
    for (int u = 0; u < 8; ++u) {
        int row = i0 + ty8 + u;
#pragma unroll
        for (int v = 0; v < 8; ++v) {
            int col = j0 + tx8 + v;
            float wf = g_Wf[(size_t)row * NTOK + col];
            float ww = (wf < thr) ? wf * invthr : 1.0f;
            g_P[(size_t)row * NTOK + col] = fexp(acc[u][v] * sc * ww);
        }
    }
}

// ---------------- K4b: attn row sums (deterministic) -----------------------
__global__ __launch_bounds__(256) void k_rowsumP() {
    __shared__ float sh[32];
    int row = blockIdx.x;
    float s = 0.0f;
    for (int c = threadIdx.x; c < NTOK; c += 256) s += g_P[(size_t)row * NTOK + c];
    s = blockAllReduce(s, sh);
    if (threadIdx.x == 0) g_rowsum[row] = s;
}

// ---------------- K4c: out = (P @ V) / rowsum ------------------------------
__global__ __launch_bounds__(256) void k_av() {
    __shared__ __align__(16) float As[16][132];
    __shared__ __align__(16) float Bs[16][132];
    int i0 = blockIdx.y * 128, j0 = blockIdx.x * 128;  // gridDim = (6, 24)
    int tid = threadIdx.x, ty8 = (tid >> 4) << 3, tx8 = (tid & 15) << 3;
    float acc[8][8] = {};
    for (int kt = 0; kt < NTOK; kt += 16) {
        load_panel_T(As, g_P + (size_t)i0 * NTOK + kt, NTOK);
        load_panel_N(Bs, g_V + (size_t)kt * DMODEL + j0, DMODEL);
        __syncthreads();
        micro16(As, Bs, acc, ty8, tx8);
        __syncthreads();
    }
#pragma unroll
    for (int u = 0; u < 8; ++u) {
        int row = i0 + ty8 + u;
        float ir = 1.0f / g_rowsum[row];
#pragma unroll
        for (int v = 0; v < 8; ++v)
            g_att[(size_t)row * DMODEL + j0 + tx8 + v] = acc[u][v] * ir;
    }
}

// ---------------- K5: residual + LayerNorm ---------------------------------
__global__ __launch_bounds__(256) void k_ln(const float* __restrict__ h_s,
                                            const float* __restrict__ gamma,
                                            const float* __restrict__ beta,
                                            float* __restrict__ y) {
    __shared__ float sh[32];
    int row = blockIdx.x, t = threadIdx.x;
    const float* hp = h_s + (size_t)row * DMODEL;
    const float* op = g_att + (size_t)row * DMODEL;
    float x0 = hp[t] + op[t];
    float x1 = hp[t + 256] + op[t + 256];
    float x2 = hp[t + 512] + op[t + 512];
    float s = blockAllReduce(x0 + x1 + x2, sh);
    float mean = s * (1.0f / (float)DMODEL);
    float d0 = x0 - mean, d1 = x1 - mean, d2 = x2 - mean;
    float v = blockAllReduce(d0 * d0 + d1 * d1 + d2 * d2, sh);
    float rstd = rsqrtf(v * (1.0f / (float)DMODEL) + 1e-5f);
    float* yp = y + (size_t)row * DMODEL;
    yp[t] = d0 * rstd * gamma[t] + beta[t];
    yp[t + 256] = d1 * rstd * gamma[t + 256] + beta[t + 256];
    yp[t + 512] = d2 * rstd * gamma[t + 512] + beta[t + 512];
}

// ---------------- launch ----------------------------------------------------
extern "C" void kernel_launch(void* const* d_in, const int* in_sizes, int n_in,
                              void* d_out, int out_size) {
    (void)in_sizes; (void)n_in; (void)out_size;
    const float* h_a = (const float*)d_in[0];
    const float* h_s = (const float*)d_in[1];
    const float* dep = (const float*)d_in[2];
    const float* Wq_a = (const float*)d_in[3];
    const float* bq_a = (const float*)d_in[4];
    const float* Wk_a = (const float*)d_in[5];
    const float* bk_a = (const float*)d_in[6];
    const float* Wq = (const float*)d_in[7];
    const float* bq = (const float*)d_in[8];
    const float* Wk = (const float*)d_in[9];
    const float* bk = (const float*)d_in[10];
    const float* Wv = (const float*)d_in[11];
    const float* bv = (const float*)d_in[12];
    const float* ln_g = (const float*)d_in[13];
    const float* ln_b = (const float*)d_in[14];
    float* out = (float*)d_out;

    k_proj<<<dim3(6, 24, 5), 256>>>(h_a, h_s, Wq_a, bq_a, Wk_a, bk_a,
                                    Wq, bq, Wk, bk, Wv, bv);
    k_hrowsum<<<dim3(NHEAD, 24), 256>>>();
    k_wf<<<dim3(24, 24), 256>>>(dep);
    k_thr<<<1, NWF_CTAS>>>();
    k_scores<<<dim3(24, 24), 256>>>();
    k_rowsumP<<<NTOK, 256>>>();
    k_av<<<dim3(6, 24), 256>>>();
    k_ln<<<NTOK, 256>>>(h_s, ln_g, ln_b, out);
}

// round 3
// speedup vs baseline: 4.4587x; 4.4587x over previous
#include <cuda_runtime.h>
#include <cuda_fp16.h>
#include <cstdint>

#define NTOK 3072
#define DMODEL 768
#define NHEAD 12
#define HDIM 64
#define NWF_CTAS 576

// ---------------- fp16/fp32 scratch (device globals) -----------------------
__device__ __align__(16) __half g_ha16[NTOK * DMODEL];
__device__ __align__(16) __half g_hs16[NTOK * DMODEL];
__device__ __align__(16) __half g_W16[5][DMODEL * DMODEL];
__device__ __align__(16) __half g_qa16[NTOK * DMODEL];
__device__ __align__(16) __half g_ka16[NTOK * DMODEL];
__device__ __align__(16) __half g_Q16[NTOK * DMODEL];
__device__ __align__(16) __half g_K16[NTOK * DMODEL];
__device__ __align__(16) __half g_Vt16[DMODEL * NTOK];          // transposed V
__device__ __align__(16) __half g_Wf16[(size_t)NTOK * NTOK];
__device__ __align__(16) __half g_P16[(size_t)NTOK * NTOK];
__device__ float g_R[NTOK * NHEAD];
__device__ float g_rowsum[NTOK];
__device__ float g_part[2 * NWF_CTAS];
__device__ float g_thr[2];
__device__ __align__(16) float g_att[NTOK * DMODEL];

// ---------------- PTX helpers ----------------------------------------------
__device__ __forceinline__ uint32_t cvta_s(const void* p) {
    return (uint32_t)__cvta_generic_to_shared(p);
}
__device__ __forceinline__ void ldsm_x4(uint32_t& r0, uint32_t& r1, uint32_t& r2,
                                        uint32_t& r3, uint32_t a) {
    asm volatile("ldmatrix.sync.aligned.m8n8.x4.shared.b16 {%0,%1,%2,%3}, [%4];"
                 : "=r"(r0), "=r"(r1), "=r"(r2), "=r"(r3) : "r"(a));
}
__device__ __forceinline__ void hmma(float* c, uint32_t a0, uint32_t a1, uint32_t a2,
                                     uint32_t a3, uint32_t b0, uint32_t b1) {
    asm volatile(
        "mma.sync.aligned.m16n8k16.row.col.f32.f16.f16.f32 "
        "{%0,%1,%2,%3},{%4,%5,%6,%7},{%8,%9},{%0,%1,%2,%3};"
        : "+f"(c[0]), "+f"(c[1]), "+f"(c[2]), "+f"(c[3])
        : "r"(a0), "r"(a1), "r"(a2), "r"(a3), "r"(b0), "r"(b1));
}
__device__ __forceinline__ void cp16(uint32_t s, const void* g) {
    asm volatile("cp.async.cg.shared.global [%0], [%1], 16;" ::"r"(s), "l"(g));
}
__device__ __forceinline__ void cp_commit() { asm volatile("cp.async.commit_group;"); }
__device__ __forceinline__ void cp_wait0() { asm volatile("cp.async.wait_group 0;"); }

// ---------------- smem tile helpers ----------------------------------------
// One operand tile = 128 rows x 32 halves = 8192 bytes (4 16B chunks per row).
// Physical chunk = chunk ^ ((row>>1)&3): conflict-free stores & ldmatrix.
#define TILE_BYTES 8192

__device__ __forceinline__ void load_tile(uint32_t sbase, const __half* g, int ld,
                                          int tid) {
#pragma unroll
    for (int i = 0; i < 2; ++i) {
        int ch = tid + i * 256;     // 0..511 16B chunks
        int r = ch >> 2, c = ch & 3;
        cp16(sbase + r * 64 + ((c ^ ((r >> 1) & 3)) << 4), g + (size_t)r * ld + c * 8);
    }
}
__device__ __forceinline__ uint32_t frag_addr(uint32_t sbase, int r0, int c0, int lane) {
    int mat = lane >> 3;
    int row = r0 + (lane & 7) + ((mat & 1) << 3);
    int c = c0 + (mat >> 1);
    return sbase + row * 64 + ((c ^ ((row >> 1) & 3)) << 4);
}

// compute one 128x128x32 step: warp tile 64x32, acc[4 m16][4 n8][4]
__device__ __forceinline__ void mma_tile(uint32_t sA, uint32_t sB,
                                         float (&acc)[4][4][4], int wm, int wn,
                                         int lane) {
#pragma unroll
    for (int ks = 0; ks < 2; ++ks) {
        uint32_t a[4][4];
#pragma unroll
        for (int mi = 0; mi < 4; ++mi)
            ldsm_x4(a[mi][0], a[mi][1], a[mi][2], a[mi][3],
                    frag_addr(sA, wm * 64 + mi * 16, ks * 2, lane));
        uint32_t b[2][4];
#pragma unroll
        for (int nb = 0; nb < 2; ++nb)
            ldsm_x4(b[nb][0], b[nb][1], b[nb][2], b[nb][3],
                    frag_addr(sB, wn * 32 + nb * 16, ks * 2, lane));
#pragma unroll
        for (int mi = 0; mi < 4; ++mi)
#pragma unroll
            for (int nb = 0; nb < 2; ++nb) {
                hmma(acc[mi][2 * nb], a[mi][0], a[mi][1], a[mi][2], a[mi][3],
                     b[nb][0], b[nb][2]);
                hmma(acc[mi][2 * nb + 1], a[mi][0], a[mi][1], a[mi][2], a[mi][3],
                     b[nb][1], b[nb][3]);
            }
    }
}

// full pipelined NT GEMM: C_tile(128x128) = A(128xK) * B(128xK)^T
// smem layout: A buffers at sAb + {0, 8192}; B buffers at sBb + {0, 8192}.
__device__ __forceinline__ void gemm_nt(const __half* A, int lda, const __half* B,
                                        int ldb, int kIters, float (&acc)[4][4][4],
                                        uint32_t sAb, uint32_t sBb, int tid, int wm,
                                        int wn, int lane) {
    load_tile(sAb, A, lda, tid);
    load_tile(sBb, B, ldb, tid);
    cp_commit();
    for (int kt = 0; kt < kIters; ++kt) {
        cp_wait0();
        __syncthreads();
        if (kt + 1 < kIters) {
            load_tile(sAb + ((kt + 1) & 1) * TILE_BYTES, A + (kt + 1) * 32, lda, tid);
            load_tile(sBb + ((kt + 1) & 1) * TILE_BYTES, B + (kt + 1) * 32, ldb, tid);
        }
        cp_commit();
        mma_tile(sAb + (kt & 1) * TILE_BYTES, sBb + (kt & 1) * TILE_BYTES, acc, wm, wn,
                 lane);
        __syncthreads();
    }
}

// ---------------- deterministic block reduce -------------------------------
__device__ __forceinline__ float blockAllReduce(float v, float* sh) {
    int lane = threadIdx.x & 31;
    int w = threadIdx.x >> 5;
    int nw = (blockDim.x + 31) >> 5;
#pragma unroll
    for (int o = 16; o > 0; o >>= 1) v += __shfl_xor_sync(0xffffffffu, v, o);
    __syncthreads();
    if (lane == 0) sh[w] = v;
    __syncthreads();
    if (w == 0) {
        float r = (lane < nw) ? sh[lane] : 0.0f;
#pragma unroll
        for (int o = 16; o > 0; o >>= 1) r += __shfl_xor_sync(0xffffffffu, r, o);
        if (lane == 0) sh[0] = r;
    }
    __syncthreads();
    return sh[0];
}

// ---------------- K0: fp32 -> fp16 conversions -----------------------------
__global__ __launch_bounds__(256) void k_cvt(const float* s0, const float* s1,
                                             const float* s2, const float* s3,
                                             const float* s4, const float* s5,
                                             const float* s6) {
    const float* src[7] = {s0, s1, s2, s3, s4, s5, s6};
    __half* dst[7] = {g_ha16, g_hs16, g_W16[0], g_W16[1], g_W16[2], g_W16[3], g_W16[4]};
    const int n4[7] = {NTOK * DMODEL / 4, NTOK * DMODEL / 4, DMODEL * DMODEL / 4,
                       DMODEL * DMODEL / 4, DMODEL * DMODEL / 4, DMODEL * DMODEL / 4,
                       DMODEL * DMODEL / 4};
    int y = blockIdx.y;
    int t = blockIdx.x * 256 + threadIdx.x;
    if (t < n4[y]) {
        float4 v = ((const float4*)src[y])[t];
        __half2* D = (__half2*)dst[y];
        D[2 * t] = __floats2half2_rn(v.x, v.y);
        D[2 * t + 1] = __floats2half2_rn(v.z, v.w);
    }
}

// ---------------- K1: five projections, NT GEMM + bias ---------------------
__global__ __launch_bounds__(256) void k_proj(const float* b0, const float* b1,
                                              const float* b2, const float* b3,
                                              const float* b4) {
    __shared__ __align__(16) __half smem[16384];  // 32 KB: A 2x8K, B 2x8K
    int z = blockIdx.z;
    const __half* A = (z < 2) ? g_ha16 : g_hs16;
    const __half* B = g_W16[z];
    const float* bias = (z == 0) ? b0 : (z == 1) ? b1 : (z == 2) ? b2 : (z == 3) ? b3 : b4;
    __half* C = (z == 0) ? g_qa16 : (z == 1) ? g_ka16 : (z == 2) ? g_Q16
                : (z == 3) ? g_K16 : nullptr;
    int i0 = blockIdx.y * 128, j0 = blockIdx.x * 128;
    int tid = threadIdx.x, lane = tid & 31, w = tid >> 5, wm = w >> 2, wn = w & 3;
    uint32_t sAb = cvta_s(smem);
    float acc[4][4][4] = {};
    gemm_nt(A + (size_t)i0 * DMODEL, DMODEL, B + (size_t)j0 * DMODEL, DMODEL, 24, acc,
            sAb, sAb + 2 * TILE_BYTES, tid, wm, wn, lane);
    int rb = i0 + wm * 64, cb = j0 + wn * 32;
#pragma unroll
    for (int mi = 0; mi < 4; ++mi) {
        int r0 = rb + mi * 16 + (lane >> 2), r1 = r0 + 8;
#pragma unroll
        for (int nj = 0; nj < 4; ++nj) {
            int col = cb + nj * 8 + (lane & 3) * 2;
            float2 bv = *(const float2*)&bias[col];
            float v0 = acc[mi][nj][0] + bv.x, v1 = acc[mi][nj][1] + bv.y;
            float v2 = acc[mi][nj][2] + bv.x, v3 = acc[mi][nj][3] + bv.y;
            if (z < 4) {
                *(__half2*)&C[(size_t)r0 * DMODEL + col] = __floats2half2_rn(v0, v1);
                *(__half2*)&C[(size_t)r1 * DMODEL + col] = __floats2half2_rn(v2, v3);
            } else {
                g_Vt16[(size_t)col * NTOK + r0] = __float2half_rn(v0);
                g_Vt16[(size_t)(col + 1) * NTOK + r0] = __float2half_rn(v1);
                g_Vt16[(size_t)col * NTOK + r1] = __float2half_rn(v2);
                g_Vt16[(size_t)(col + 1) * NTOK + r1] = __float2half_rn(v3);
            }
        }
    }
}

// ---------------- K2a: per-head softmax denominators R[i,h] ----------------
// grid (24 i-tiles, 12 heads). A (qa slice, 64 deep) resident; stream ka over j.
__global__ __launch_bounds__(256) void k_hrowsum() {
    __shared__ __align__(16) __half sA[2][4096];
    __shared__ __align__(16) __half sB[2][4096];
    __shared__ float red[128][5];
    int i0 = blockIdx.x * 128, h = blockIdx.y;
    int tid = threadIdx.x, lane = tid & 31, w = tid >> 5, wm = w >> 2, wn = w & 3;
    const __half* A = g_qa16 + (size_t)i0 * DMODEL + h * HDIM;
    const __half* Bb = g_ka16 + h * HDIM;
    uint32_t sAa[2] = {cvta_s(sA[0]), cvta_s(sA[1])};
    uint32_t sBa[2] = {cvta_s(sB[0]), cvta_s(sB[1])};
    load_tile(sAa[0], A, DMODEL, tid);
    load_tile(sAa[1], A + 32, DMODEL, tid);
    load_tile(sBa[0], Bb, DMODEL, tid);
    cp_commit();
    float rs[8] = {};
    float acc[4][4][4] = {};
    for (int jk = 0; jk < 48; ++jk) {
        cp_wait0();
        __syncthreads();
        if (jk + 1 < 48) {
            int j1 = (jk + 1) >> 1, kk1 = (jk + 1) & 1;
            load_tile(sBa[(jk + 1) & 1], Bb + (size_t)(j1 * 128) * DMODEL + kk1 * 32,
                      DMODEL, tid);
        }
        cp_commit();
        int kk = jk & 1;
        mma_tile(sAa[kk], sBa[kk], acc, wm, wn, lane);
        __syncthreads();
        if (kk == 1) {
#pragma unroll
            for (int mi = 0; mi < 4; ++mi)
#pragma unroll
                for (int nj = 0; nj < 4; ++nj) {
                    rs[mi * 2 + 0] += __expf(acc[mi][nj][0] * 0.125f) +
                                      __expf(acc[mi][nj][1] * 0.125f);
                    rs[mi * 2 + 1] += __expf(acc[mi][nj][2] * 0.125f) +
                                      __expf(acc[mi][nj][3] * 0.125f);
                    acc[mi][nj][0] = acc[mi][nj][1] = acc[mi][nj][2] = acc[mi][nj][3] = 0.0f;
                }
        }
    }
#pragma unroll
    for (int i = 0; i < 8; ++i) {
        rs[i] += __shfl_xor_sync(0xffffffffu, rs[i], 1);
        rs[i] += __shfl_xor_sync(0xffffffffu, rs[i], 2);
    }
    if ((lane & 3) == 0) {
#pragma unroll
        for (int mi = 0; mi < 4; ++mi) {
            red[wm * 64 + mi * 16 + (lane >> 2)][wn] = rs[mi * 2];
            red[wm * 64 + mi * 16 + (lane >> 2) + 8][wn] = rs[mi * 2 + 1];
        }
    }
    __syncthreads();
    if (tid < 128)
        g_R[(i0 + tid) * NHEAD + h] = red[tid][0] + red[tid][1] + red[tid][2] + red[tid][3];
}

// ---------------- K2b: Wf = Wd * mean_h softmax_h + stats ------------------
__global__ __launch_bounds__(256, 1) void k_wf(const float* __restrict__ dep) {
    __shared__ __align__(16) __half sA[2][4096];
    __shared__ __align__(16) __half sB[2][4096];
    __shared__ float Rinv[128][NHEAD];
    __shared__ float shred[32];
    int i0 = blockIdx.y * 128, j0 = blockIdx.x * 128;
    int tid = threadIdx.x, lane = tid & 31, w = tid >> 5, wm = w >> 2, wn = w & 3;
    for (int idx = tid; idx < 128 * NHEAD; idx += 256)
        Rinv[idx / NHEAD][idx % NHEAD] = 1.0f / g_R[(i0 + idx / NHEAD) * NHEAD + idx % NHEAD];
    const __half* Ab = g_qa16 + (size_t)i0 * DMODEL;
    const __half* Bb = g_ka16 + (size_t)j0 * DMODEL;
    uint32_t sAa[2] = {cvta_s(sA[0]), cvta_s(sA[1])};
    uint32_t sBa[2] = {cvta_s(sB[0]), cvta_s(sB[1])};
    load_tile(sAa[0], Ab, DMODEL, tid);
    load_tile(sBa[0], Bb, DMODEL, tid);
    cp_commit();
    float wacc[4][4][4] = {};
    float acc[4][4][4] = {};
    for (int hk = 0; hk < 24; ++hk) {
        cp_wait0();
        __syncthreads();
        if (hk + 1 < 24) {
            int h1 = (hk + 1) >> 1, kk1 = (hk + 1) & 1;
            load_tile(sAa[(hk + 1) & 1], Ab + h1 * 64 + kk1 * 32, DMODEL, tid);
            load_tile(sBa[(hk + 1) & 1], Bb + h1 * 64 + kk1 * 32, DMODEL, tid);
        }
        cp_commit();
        mma_tile(sAa[hk & 1], sBa[hk & 1], acc, wm, wn, lane);
        __syncthreads();
        if (hk & 1) {
            int h = hk >> 1;
#pragma unroll
            for (int mi = 0; mi < 4; ++mi) {
                float ir0 = Rinv[wm * 64 + mi * 16 + (lane >> 2)][h];
                float ir1 = Rinv[wm * 64 + mi * 16 + (lane >> 2) + 8][h];
#pragma unroll
                for (int nj = 0; nj < 4; ++nj) {
                    wacc[mi][nj][0] += __expf(acc[mi][nj][0] * 0.125f) * ir0;
                    wacc[mi][nj][1] += __expf(acc[mi][nj][1] * 0.125f) * ir0;
                    wacc[mi][nj][2] += __expf(acc[mi][nj][2] * 0.125f) * ir1;
                    wacc[mi][nj][3] += __expf(acc[mi][nj][3] * 0.125f) * ir1;
                    acc[mi][nj][0] = acc[mi][nj][1] = acc[mi][nj][2] = acc[mi][nj][3] = 0.0f;
                }
            }
        }
    }
    float lsum = 0.0f, lss = 0.0f;
    const float invH = 1.0f / (float)NHEAD;
#pragma unroll
    for (int mi = 0; mi < 4; ++mi) {
        int r0 = i0 + wm * 64 + mi * 16 + (lane >> 2), r1 = r0 + 8;
#pragma unroll
        for (int nj = 0; nj < 4; ++nj) {
            int col = j0 + wn * 32 + nj * 8 + (lane & 3) * 2;
            float2 da = *(const float2*)&dep[(size_t)r0 * NTOK + col];
            float2 db = *(const float2*)&dep[(size_t)r1 * NTOK + col];
            float w0 = __expf(-0.5f * da.x * da.x) * (wacc[mi][nj][0] * invH);
            float w1 = __expf(-0.5f * da.y * da.y) * (wacc[mi][nj][1] * invH);
            float w2 = __expf(-0.5f * db.x * db.x) * (wacc[mi][nj][2] * invH);
            float w3 = __expf(-0.5f * db.y * db.y) * (wacc[mi][nj][3] * invH);
            *(__half2*)&g_Wf16[(size_t)r0 * NTOK + col] = __floats2half2_rn(w0, w1);
            *(__half2*)&g_Wf16[(size_t)r1 * NTOK + col] = __floats2half2_rn(w2, w3);
            lsum += w0 + w1 + w2 + w3;
            lss += w0 * w0 + w1 * w1 + w2 * w2 + w3 * w3;
        }
    }
    lsum = blockAllReduce(lsum, shred);
    lss = blockAllReduce(lss, shred);
    if (tid == 0) {
        int c = blockIdx.y * gridDim.x + blockIdx.x;
        g_part[c] = lsum;
        g_part[NWF_CTAS + c] = lss;
    }
}

// ---------------- K3: threshold --------------------------------------------
__global__ void k_thr() {
    __shared__ float sh[32];
    float s = g_part[threadIdx.x];
    float ss = g_part[NWF_CTAS + threadIdx.x];
    s = blockAllReduce(s, sh);
    ss = blockAllReduce(ss, sh);
    if (threadIdx.x == 0) {
        double M = (double)NTOK * (double)NTOK;
        double mean = (double)s / M;
        double var = ((double)ss - (double)s * (double)s / M) / (M - 1.0);
        if (var < 0.0) var = 0.0;
        float thr = (float)(mean + 0.5 * sqrt(var));
        g_thr[0] = thr;
        g_thr[1] = 1.0f / thr;
    }
}

// ---------------- K4a: P = exp(scores * Ww) --------------------------------
__global__ __launch_bounds__(256) void k_scores() {
    __shared__ __align__(16) __half smem[16384];
    int i0 = blockIdx.y * 128, j0 = blockIdx.x * 128;
    int tid = threadIdx.x, lane = tid & 31, w = tid >> 5, wm = w >> 2, wn = w & 3;
    uint32_t sAb = cvta_s(smem);
    float acc[4][4][4] = {};
    gemm_nt(g_Q16 + (size_t)i0 * DMODEL, DMODEL, g_K16 + (size_t)j0 * DMODEL, DMODEL,
            24, acc, sAb, sAb + 2 * TILE_BYTES, tid, wm, wn, lane);
    float thr = g_thr[0], it = g_thr[1];
    const float sc = 0.03608439182435161f;  // 1/sqrt(768)
#pragma unroll
    for (int mi = 0; mi < 4; ++mi) {
        int r0 = i0 + wm * 64 + mi * 16 + (lane >> 2), r1 = r0 + 8;
#pragma unroll
        for (int nj = 0; nj < 4; ++nj) {
            int col = j0 + wn * 32 + nj * 8 + (lane & 3) * 2;
            float2 wa = __half22float2(*(const __half2*)&g_Wf16[(size_t)r0 * NTOK + col]);
            float2 wb = __half22float2(*(const __half2*)&g_Wf16[(size_t)r1 * NTOK + col]);
            float w0 = (wa.x < thr) ? wa.x * it : 1.0f;
            float w1 = (wa.y < thr) ? wa.y * it : 1.0f;
            float w2 = (wb.x < thr) ? wb.x * it : 1.0f;
            float w3 = (wb.y < thr) ? wb.y * it : 1.0f;
            float p0 = __expf(acc[mi][nj][0] * sc * w0);
            float p1 = __expf(acc[mi][nj][1] * sc * w1);
            float p2 = __expf(acc[mi][nj][2] * sc * w2);
            float p3 = __expf(acc[mi][nj][3] * sc * w3);
            *(__half2*)&g_P16[(size_t)r0 * NTOK + col] = __floats2half2_rn(p0, p1);
            *(__half2*)&g_P16[(size_t)r1 * NTOK + col] = __floats2half2_rn(p2, p3);
        }
    }
}

// ---------------- K4b: attn row sums ---------------------------------------
__global__ __launch_bounds__(256) void k_rowsumP() {
    __shared__ float sh[32];
    int row = blockIdx.x;
    const __half2* p = (const __half2*)(g_P16 + (size_t)row * NTOK);
    float s = 0.0f;
    for (int c = threadIdx.x; c < NTOK / 2; c += 256) {
        float2 v = __half22float2(p[c]);
        s += v.x + v.y;
    }
    s = blockAllReduce(s, sh);
    if (threadIdx.x == 0) g_rowsum[row] = s;
}

// ---------------- K4c: att = (P @ V) / rowsum ------------------------------
__global__ __launch_bounds__(256) void k_av() {
    __shared__ __align__(16) __half smem[16384];
    int i0 = blockIdx.y * 128, j0 = blockIdx.x * 128;  // grid (6, 24)
    int tid = threadIdx.x, lane = tid & 31, w = tid >> 5, wm = w >> 2, wn = w & 3;
    uint32_t sAb = cvta_s(smem);
    float acc[4][4][4] = {};
    gemm_nt(g_P16 + (size_t)i0 * NTOK, NTOK, g_Vt16 + (size_t)j0 * NTOK, NTOK, 96, acc,
            sAb, sAb + 2 * TILE_BYTES, tid, wm, wn, lane);
#pragma unroll
    for (int mi = 0; mi < 4; ++mi) {
        int r0 = i0 + wm * 64 + mi * 16 + (lane >> 2), r1 = r0 + 8;
        float ir0 = 1.0f / g_rowsum[r0];
        float ir1 = 1.0f / g_rowsum[r1];
#pragma unroll
        for (int nj = 0; nj < 4; ++nj) {
            int col = j0 + wn * 32 + nj * 8 + (lane & 3) * 2;
            *(float2*)&g_att[(size_t)r0 * DMODEL + col] =
                make_float2(acc[mi][nj][0] * ir0, acc[mi][nj][1] * ir0);
            *(float2*)&g_att[(size_t)r1 * DMODEL + col] =
                make_float2(acc[mi][nj][2] * ir1, acc[mi][nj][3] * ir1);
        }
    }
}

// ---------------- K5: residual + LayerNorm ---------------------------------
__global__ __launch_bounds__(256) void k_ln(const float* __restrict__ h_s,
                                            const float* __restrict__ gamma,
                                            const float* __restrict__ beta,
                                            float* __restrict__ y) {
    __shared__ float sh[32];
    int row = blockIdx.x, t = threadIdx.x;
    const float* hp = h_s + (size_t)row * DMODEL;
    const float* op = g_att + (size_t)row * DMODEL;
    float x0 = hp[t] + op[t];
    float x1 = hp[t + 256] + op[t + 256];
    float x2 = hp[t + 512] + op[t + 512];
    float s = blockAllReduce(x0 + x1 + x2, sh);
    float mean = s * (1.0f / (float)DMODEL);
    float d0 = x0 - mean, d1 = x1 - mean, d2 = x2 - mean;
    float v = blockAllReduce(d0 * d0 + d1 * d1 + d2 * d2, sh);
    float rstd = rsqrtf(v * (1.0f / (float)DMODEL) + 1e-5f);
    float* yp = y + (size_t)row * DMODEL;
    yp[t] = d0 * rstd * gamma[t] + beta[t];
    yp[t + 256] = d1 * rstd * gamma[t + 256] + beta[t + 256];
    yp[t + 512] = d2 * rstd * gamma[t + 512] + beta[t + 512];
}

// ---------------- launch ----------------------------------------------------
extern "C" void kernel_launch(void* const* d_in, const int* in_sizes, int n_in,
                              void* d_out, int out_size) {
    (void)in_sizes; (void)n_in; (void)out_size;
    const float* h_a = (const float*)d_in[0];
    const float* h_s = (const float*)d_in[1];
    const float* dep = (const float*)d_in[2];
    const float* Wq_a = (const float*)d_in[3];
    const float* bq_a = (const float*)d_in[4];
    const float* Wk_a = (const float*)d_in[5];
    const float* bk_a = (const float*)d_in[6];
    const float* Wq = (const float*)d_in[7];
    const float* bq = (const float*)d_in[8];
    const float* Wk = (const float*)d_in[9];
    const float* bk = (const float*)d_in[10];
    const float* Wv = (const float*)d_in[11];
    const float* bv = (const float*)d_in[12];
    const float* ln_g = (const float*)d_in[13];
    const float* ln_b = (const float*)d_in[14];
    float* out = (float*)d_out;

    k_cvt<<<dim3(2304, 7), 256>>>(h_a, h_s, Wq_a, Wk_a, Wq, Wk, Wv);
    k_proj<<<dim3(6, 24, 5), 256>>>(bq_a, bk_a, bq, bk, bv);
    k_hrowsum<<<dim3(24, NHEAD), 256>>>();
    k_wf<<<dim3(24, 24), 256>>>(dep);
    k_thr<<<1, NWF_CTAS>>>();
    k_scores<<<dim3(24, 24), 256>>>();
    k_rowsumP<<<NTOK, 256>>>();
    k_av<<<dim3(6, 24), 256>>>();
    k_ln<<<NTOK, 256>>>(h_s, ln_g, ln_b, out);
}